// round 10
// baseline (speedup 1.0000x reference)
#include <cuda_runtime.h>

// DiarizationLoss: B=32, T=65536, S=4, scalar output.
// Single fused kernel, statically balanced tile partition over active elements.

#define NB 32
#define NT 65536
#define CEPS 1e-7f
#define LN2F 0.69314718055994531f

#define THREADS 256
#define TILE_T 1024                 // elements per tile (= THREADS * 4)
#define GRID 456                    // 3 blocks/SM x 152 SMs: exactly one wave

__device__ float g_part[NB][21];
__device__ unsigned int g_count;

// lengths dtype probe: values in [32768,65536), nonzero.
// int64 LE => word1 (hi of lengths[0]) == 0 ; int32 => word1 >= 32768.
__device__ __forceinline__ int load_len(const int* __restrict__ p32, int b) {
    return (p32[1] == 0) ? p32[2 * b] : p32[b];
}

__global__ __launch_bounds__(THREADS, 3) void diar_loss_kernel(
    const float* __restrict__ ps,
    const float* __restrict__ pv,
    const float* __restrict__ lb,
    const float* __restrict__ vad,
    const int*   __restrict__ len32,
    float*       __restrict__ out)
{
    const int tid = threadIdx.x;

    __shared__ int s_len[NB];
    __shared__ int s_prefix[NB + 1];     // tile-count prefix
    __shared__ float sm[21][8];

    if (tid < 32) {
        int l = load_len(len32, tid);
        s_len[tid] = l;
        int x = (l + TILE_T - 1) >> 10;          // active tiles for this batch
        #pragma unroll
        for (int o = 1; o < 32; o <<= 1) {       // inclusive warp scan
            int y = __shfl_up_sync(0xffffffffu, x, o);
            if (tid >= o) x += y;
        }
        s_prefix[tid + 1] = x;
        if (tid == 0) s_prefix[0] = 0;
    }
    __syncthreads();

    const int ntile = s_prefix[NB];
    const int start = (int)(((long long)blockIdx.x * ntile) / GRID);
    const int end   = (int)(((long long)(blockIdx.x + 1) * ntile) / GRID);

    float acc[21];
    #pragma unroll
    for (int k = 0; k < 21; k++) acc[k] = 0.0f;
    int cur_b = -1;

    const int lane = tid & 31;
    const int w    = tid >> 5;

    auto flush = [&](int bb) {
        #pragma unroll
        for (int k = 0; k < 21; k++) {
            float v = acc[k];
            v += __shfl_down_sync(0xffffffffu, v, 16);
            v += __shfl_down_sync(0xffffffffu, v, 8);
            v += __shfl_down_sync(0xffffffffu, v, 4);
            v += __shfl_down_sync(0xffffffffu, v, 2);
            v += __shfl_down_sync(0xffffffffu, v, 1);
            if (lane == 0) sm[k][w] = v;
            acc[k] = 0.0f;
        }
        __syncthreads();
        if (tid < 21) {
            float v = 0.0f;
            #pragma unroll
            for (int ww = 0; ww < 8; ww++) v += sm[tid][ww];
            atomicAdd(&g_part[bb][tid], v);
        }
        __syncthreads();
    };

    int b = 0;
    for (int tile = start; tile < end; tile++) {
        while (tile >= s_prefix[b + 1]) b++;     // tiles are batch-major ascending
        if (b != cur_b) { if (cur_b >= 0) flush(cur_b); cur_b = b; }

        const int len = s_len[b];
        const int t0  = (tile - s_prefix[b]) << 10;   // 1024-aligned in-batch offset

        const float4* __restrict__ psb  = (const float4*)(ps + (size_t)b * NT * 4);
        const float4* __restrict__ lbb  = (const float4*)(lb + (size_t)b * NT * 4);
        const float4* __restrict__ pv4b = (const float4*)(pv  + (size_t)b * NT);
        const float4* __restrict__ v4b  = (const float4*)(vad + (size_t)b * NT);

        // base-2 logs; ln2 folded into finalize. m in {0,1} applies length mask.
        auto elem = [&](float4 p4, float4 l4, float pvv, float v, float m) {
            float pp[4] = {p4.x, p4.y, p4.z, p4.w};
            float ll[4] = {l4.x * m, l4.y * m, l4.z * m, l4.w * m};
            float d[4];
            #pragma unroll
            for (int i = 0; i < 4; i++) {
                float p  = fminf(fmaxf(pp[i], CEPS), 1.0f - CEPS);
                float lq = __log2f(1.0f - p);
                float lp = __log2f(p);
                d[i] = lp - lq;
                acc[16 + i] += lq * m;
            }
            #pragma unroll
            for (int i = 0; i < 4; i++)
                #pragma unroll
                for (int j = 0; j < 4; j++)
                    acc[i * 4 + j] += d[i] * ll[j];
            pvv = fminf(fmaxf(pvv, CEPS), 1.0f - CEPS);
            float arg = (v > 0.5f) ? pvv : (1.0f - pvv);
            acc[20] -= __log2f(arg) * m;
        };

        // one tile = 4 consecutive elements per thread, 10 independent LDG.128
        const int tg = t0 + 4 * tid;
        float4 P0 = psb[tg],     P1 = psb[tg + 1];
        float4 P2 = psb[tg + 2], P3 = psb[tg + 3];
        float4 L0 = lbb[tg],     L1 = lbb[tg + 1];
        float4 L2 = lbb[tg + 2], L3 = lbb[tg + 3];
        float4 pv4 = pv4b[tg >> 2];
        float4 v4  = v4b[tg >> 2];
        float m0 = (tg     < len) ? 1.0f : 0.0f;
        float m1 = (tg + 1 < len) ? 1.0f : 0.0f;
        float m2 = (tg + 2 < len) ? 1.0f : 0.0f;
        float m3 = (tg + 3 < len) ? 1.0f : 0.0f;
        elem(P0, L0, pv4.x, v4.x, m0);
        elem(P1, L1, pv4.y, v4.y, m1);
        elem(P2, L2, pv4.z, v4.z, m2);
        elem(P3, L3, pv4.w, v4.w, m3);
    }
    if (cur_b >= 0) flush(cur_b);

    // ---- last-block finalize ----
    __shared__ int s_last;
    if (tid == 0) {
        __threadfence();
        unsigned prev = atomicAdd(&g_count, 1u);
        s_last = (prev == (unsigned)(GRID - 1));
    }
    __syncthreads();
    if (!s_last) return;
    __threadfence();

    if (tid < NB) {
        const int bb = tid;
        const float msum = (float)s_len[bb];
        const float scal = LN2F / msum;   // fold ln2 (base-2 logs) here

        float L[4][4];
        #pragma unroll
        for (int i = 0; i < 4; i++)
            #pragma unroll
            for (int j = 0; j < 4; j++)
                L[i][j] = -(g_part[bb][i * 4 + j] + g_part[bb][16 + i]) * scal;

        float best = 3.4e38f;
        #pragma unroll
        for (int a = 0; a < 4; a++)
            #pragma unroll
            for (int cc = 0; cc < 4; cc++) {
                if (cc == a) continue;
                #pragma unroll
                for (int e = 0; e < 4; e++) {
                    if (e == a || e == cc) continue;
                    int f = 6 - a - cc - e;
                    best = fminf(best, L[0][a] + L[1][cc] + L[2][e] + L[3][f]);
                }
            }
        best *= 0.25f;

        float sb = best, sv = g_part[bb][20] * LN2F, sd = msum;
        #pragma unroll
        for (int off = 16; off >= 1; off >>= 1) {
            sb += __shfl_xor_sync(0xffffffffu, sb, off);
            sv += __shfl_xor_sync(0xffffffffu, sv, off);
            sd += __shfl_xor_sync(0xffffffffu, sd, off);
        }
        if (bb == 0)
            out[0] = (sb / (float)NB) + 0.5f * (sv / sd);
    }
    __syncthreads();

    // reset scratch for next graph replay
    for (int i = tid; i < NB * 21; i += THREADS)
        ((float*)g_part)[i] = 0.0f;
    if (tid == 0) g_count = 0u;
}

extern "C" void kernel_launch(void* const* d_in, const int* in_sizes, int n_in,
                              void* d_out, int out_size)
{
    diar_loss_kernel<<<GRID, THREADS>>>(
        (const float*)d_in[0], (const float*)d_in[1],
        (const float*)d_in[2], (const float*)d_in[3],
        (const int*)d_in[4], (float*)d_out);
}

// round 11
// speedup vs baseline: 1.1481x; 1.1481x over previous
#include <cuda_runtime.h>

// DiarizationLoss: B=32, T=65536, S=4, scalar output.
// Balanced tile partition + coalesced stride-THREADS loads (min L1tex wavefronts).

#define NB 32
#define NT 65536
#define CEPS 1e-7f
#define LN2F 0.69314718055994531f

#define THREADS 256
#define TILE_T 1024                 // elements per tile
#define GRID 608                    // 4 blocks/SM x 152 SMs: exactly one wave

__device__ float g_part[NB][21];
__device__ unsigned int g_count;

// lengths dtype probe: values in [32768,65536), nonzero.
// int64 LE => word1 (hi of lengths[0]) == 0 ; int32 => word1 >= 32768.
__device__ __forceinline__ int load_len(const int* __restrict__ p32, int b) {
    return (p32[1] == 0) ? p32[2 * b] : p32[b];
}

__global__ __launch_bounds__(THREADS, 4) void diar_loss_kernel(
    const float* __restrict__ ps,
    const float* __restrict__ pv,
    const float* __restrict__ lb,
    const float* __restrict__ vad,
    const int*   __restrict__ len32,
    float*       __restrict__ out)
{
    const int tid = threadIdx.x;

    __shared__ int s_len[NB];
    __shared__ int s_prefix[NB + 1];
    __shared__ float sm[21][8];

    if (tid < 32) {
        int l = load_len(len32, tid);
        s_len[tid] = l;
        int x = (l + TILE_T - 1) >> 10;          // active tiles for this batch
        #pragma unroll
        for (int o = 1; o < 32; o <<= 1) {       // inclusive warp scan
            int y = __shfl_up_sync(0xffffffffu, x, o);
            if (tid >= o) x += y;
        }
        s_prefix[tid + 1] = x;
        if (tid == 0) s_prefix[0] = 0;
    }
    __syncthreads();

    const int ntile = s_prefix[NB];
    const int start = (int)(((long long)blockIdx.x * ntile) / GRID);
    const int end   = (int)(((long long)(blockIdx.x + 1) * ntile) / GRID);

    float acc[21];
    #pragma unroll
    for (int k = 0; k < 21; k++) acc[k] = 0.0f;
    int cur_b = -1;

    const int lane = tid & 31;
    const int w    = tid >> 5;

    auto flush = [&](int bb) {
        #pragma unroll
        for (int k = 0; k < 21; k++) {
            float v = acc[k];
            v += __shfl_down_sync(0xffffffffu, v, 16);
            v += __shfl_down_sync(0xffffffffu, v, 8);
            v += __shfl_down_sync(0xffffffffu, v, 4);
            v += __shfl_down_sync(0xffffffffu, v, 2);
            v += __shfl_down_sync(0xffffffffu, v, 1);
            if (lane == 0) sm[k][w] = v;
            acc[k] = 0.0f;
        }
        __syncthreads();
        if (tid < 21) {
            float v = 0.0f;
            #pragma unroll
            for (int ww = 0; ww < 8; ww++) v += sm[tid][ww];
            atomicAdd(&g_part[bb][tid], v);
        }
        __syncthreads();
    };

    // one element: base-2 logs (ln2 folded into finalize)
    auto elem_fast = [&](float4 p4, float4 l4, float pvv, float v) {
        float pp[4] = {p4.x, p4.y, p4.z, p4.w};
        float ll[4] = {l4.x, l4.y, l4.z, l4.w};
        float d[4];
        #pragma unroll
        for (int i = 0; i < 4; i++) {
            float p  = fminf(fmaxf(pp[i], CEPS), 1.0f - CEPS);
            float lq = __log2f(1.0f - p);
            float lp = __log2f(p);
            d[i] = lp - lq;
            acc[16 + i] += lq;
        }
        #pragma unroll
        for (int i = 0; i < 4; i++)
            #pragma unroll
            for (int j = 0; j < 4; j++)
                acc[i * 4 + j] += d[i] * ll[j];
        pvv = fminf(fmaxf(pvv, CEPS), 1.0f - CEPS);
        float arg = (v > 0.5f) ? pvv : (1.0f - pvv);
        acc[20] -= __log2f(arg);
    };
    auto elem_mask = [&](float4 p4, float4 l4, float pvv, float v, float m) {
        float pp[4] = {p4.x, p4.y, p4.z, p4.w};
        float ll[4] = {l4.x * m, l4.y * m, l4.z * m, l4.w * m};
        float d[4];
        #pragma unroll
        for (int i = 0; i < 4; i++) {
            float p  = fminf(fmaxf(pp[i], CEPS), 1.0f - CEPS);
            float lq = __log2f(1.0f - p);
            float lp = __log2f(p);
            d[i] = lp - lq;
            acc[16 + i] += lq * m;
        }
        #pragma unroll
        for (int i = 0; i < 4; i++)
            #pragma unroll
            for (int j = 0; j < 4; j++)
                acc[i * 4 + j] += d[i] * ll[j];
        pvv = fminf(fmaxf(pvv, CEPS), 1.0f - CEPS);
        float arg = (v > 0.5f) ? pvv : (1.0f - pvv);
        acc[20] -= __log2f(arg) * m;
    };

    int b = 0;
    for (int tile = start; tile < end; tile++) {
        while (tile >= s_prefix[b + 1]) b++;     // tiles batch-major ascending
        if (b != cur_b) { if (cur_b >= 0) flush(cur_b); cur_b = b; }

        const int len = s_len[b];
        const int t0  = (tile - s_prefix[b]) << 10;

        const float4* __restrict__ psb = (const float4*)(ps + (size_t)b * NT * 4);
        const float4* __restrict__ lbb = (const float4*)(lb + (size_t)b * NT * 4);
        const float*  __restrict__ pvb = pv  + (size_t)b * NT;
        const float*  __restrict__ vb  = vad + (size_t)b * NT;

        const bool interior = (t0 + TILE_T <= len);   // block-uniform

        if (interior) {
            #pragma unroll
            for (int s = 0; s < 2; s++) {
                const int ta = t0 + tid + s * (2 * THREADS);
                const int tb = ta + THREADS;
                // 8 independent coalesced loads (4x LDG.128 + 4x LDG.32)
                float4 Pa = psb[ta], Pb = psb[tb];
                float4 La = lbb[ta], Lb = lbb[tb];
                float  pa = pvb[ta], pb = pvb[tb];
                float  va = vb[ta],  vvb = vb[tb];
                elem_fast(Pa, La, pa, va);
                elem_fast(Pb, Lb, pb, vvb);
            }
        } else {
            #pragma unroll
            for (int s = 0; s < 2; s++) {
                const int ta = t0 + tid + s * (2 * THREADS);
                const int tb = ta + THREADS;
                float4 Pa = psb[ta], Pb = psb[tb];
                float4 La = lbb[ta], Lb = lbb[tb];
                float  pa = pvb[ta], pb = pvb[tb];
                float  va = vb[ta],  vvb = vb[tb];
                float  ma = (ta < len) ? 1.0f : 0.0f;
                float  mb = (tb < len) ? 1.0f : 0.0f;
                elem_mask(Pa, La, pa, va, ma);
                elem_mask(Pb, Lb, pb, vvb, mb);
            }
        }
    }
    if (cur_b >= 0) flush(cur_b);

    // ---- last-block finalize ----
    __shared__ int s_last;
    if (tid == 0) {
        __threadfence();
        unsigned prev = atomicAdd(&g_count, 1u);
        s_last = (prev == (unsigned)(GRID - 1));
    }
    __syncthreads();
    if (!s_last) return;
    __threadfence();

    if (tid < NB) {
        const int bb = tid;
        const float msum = (float)s_len[bb];
        const float scal = LN2F / msum;

        float L[4][4];
        #pragma unroll
        for (int i = 0; i < 4; i++)
            #pragma unroll
            for (int j = 0; j < 4; j++)
                L[i][j] = -(g_part[bb][i * 4 + j] + g_part[bb][16 + i]) * scal;

        float best = 3.4e38f;
        #pragma unroll
        for (int a = 0; a < 4; a++)
            #pragma unroll
            for (int cc = 0; cc < 4; cc++) {
                if (cc == a) continue;
                #pragma unroll
                for (int e = 0; e < 4; e++) {
                    if (e == a || e == cc) continue;
                    int f = 6 - a - cc - e;
                    best = fminf(best, L[0][a] + L[1][cc] + L[2][e] + L[3][f]);
                }
            }
        best *= 0.25f;

        float sb = best, sv = g_part[bb][20] * LN2F, sd = msum;
        #pragma unroll
        for (int off = 16; off >= 1; off >>= 1) {
            sb += __shfl_xor_sync(0xffffffffu, sb, off);
            sv += __shfl_xor_sync(0xffffffffu, sv, off);
            sd += __shfl_xor_sync(0xffffffffu, sd, off);
        }
        if (bb == 0)
            out[0] = (sb / (float)NB) + 0.5f * (sv / sd);
    }
    __syncthreads();

    // reset scratch for next graph replay
    for (int i = tid; i < NB * 21; i += THREADS)
        ((float*)g_part)[i] = 0.0f;
    if (tid == 0) g_count = 0u;
}

extern "C" void kernel_launch(void* const* d_in, const int* in_sizes, int n_in,
                              void* d_out, int out_size)
{
    diar_loss_kernel<<<GRID, THREADS>>>(
        (const float*)d_in[0], (const float*)d_in[1],
        (const float*)d_in[2], (const float*)d_in[3],
        (const int*)d_in[4], (float*)d_out);
}